// round 3
// baseline (speedup 1.0000x reference)
#include <cuda_runtime.h>
#include <cfloat>

// Problem geometry (fixed by the reference): planes of 128x128, B*C planes.
constexpr int W_DIM   = 128;
constexpr int HW      = 128 * 128;     // 16384 elements per (b,c) plane
constexpr int THREADS = 1024;
constexpr int V4      = HW / 4;        // 4096 float4 per plane
constexpr int PER     = V4 / THREADS;  // 4 float4 per thread
// Sum of x coordinates over the whole plane: H * sum_{x=0..127} x = 128 * 8128
constexpr float SUM_XW = 1040384.0f;   // same for y by symmetry

__device__ __forceinline__ float warp_sum(float v) {
    #pragma unroll
    for (int o = 16; o > 0; o >>= 1) v += __shfl_down_sync(0xffffffffu, v, o);
    return v;
}
__device__ __forceinline__ float warp_min(float v) {
    #pragma unroll
    for (int o = 16; o > 0; o >>= 1) v = fminf(v, __shfl_down_sync(0xffffffffu, v, o));
    return v;
}
__device__ __forceinline__ float warp_max(float v) {
    #pragma unroll
    for (int o = 16; o > 0; o >>= 1) v = fmaxf(v, __shfl_down_sync(0xffffffffu, v, o));
    return v;
}

__global__ __launch_bounds__(THREADS, 1)
void hm2kp_kernel(const float* __restrict__ in,
                  float* __restrict__ map_out,
                  float* __restrict__ kp_out,
                  float* __restrict__ zeta_out,
                  int planes)
{
    __shared__ float s_r0[32], s_r1[32], s_r2[32], s_r3[32], s_r4[32];
    __shared__ float s_bmin, s_rcp;

    const int tid    = threadIdx.x;
    const int lane   = tid & 31;
    const int wid    = tid >> 5;
    const int stride = gridDim.x;

    int p = blockIdx.x;

    // ---- Prologue: load first plane + accumulate raw stats ----
    float4 v[PER];
    float lmin = FLT_MAX, lmax = -FLT_MAX, sr = 0.f, sxr = 0.f, syr = 0.f;
    {
        const float4* __restrict__ ip = reinterpret_cast<const float4*>(in) + (size_t)p * V4;
        #pragma unroll
        for (int i = 0; i < PER; ++i) {
            v[i] = __ldcs(&ip[tid + i * THREADS]);
            lmin = fminf(lmin, fminf(fminf(v[i].x, v[i].y), fminf(v[i].z, v[i].w)));
            lmax = fmaxf(lmax, fmaxf(fmaxf(v[i].x, v[i].y), fmaxf(v[i].z, v[i].w)));
            const int base = (tid + i * THREADS) << 2;
            const float x0 = (float)(base & (W_DIM - 1));
            const float yy = (float)(base >> 7);
            const float s4 = (v[i].x + v[i].y) + (v[i].z + v[i].w);
            sr  += s4;
            sxr += v[i].x * x0 + v[i].y * (x0 + 1.f) + v[i].z * (x0 + 2.f) + v[i].w * (x0 + 3.f);
            syr += s4 * yy;
        }
    }

    while (p < planes) {
        const int  pn       = p + stride;
        const bool has_next = pn < planes;

        // ---- Prefetch next plane BEFORE the reduce: keeps the read stream
        //      flowing through the barrier; results consumed much later. ----
        float4 u[PER];
        if (has_next) {
            const float4* __restrict__ ip = reinterpret_cast<const float4*>(in) + (size_t)pn * V4;
            #pragma unroll
            for (int i = 0; i < PER; ++i) u[i] = __ldcs(&ip[tid + i * THREADS]);
        }

        // ---- Block reduce: min, max, sum, sum*x, sum*y (32 warps) ----
        float wmin = warp_min(lmin);
        float wmax = warp_max(lmax);
        float ws   = warp_sum(sr);
        float wx   = warp_sum(sxr);
        float wy   = warp_sum(syr);
        if (lane == 0) {
            s_r0[wid] = wmin; s_r1[wid] = wmax;
            s_r2[wid] = ws;   s_r3[wid] = wx;  s_r4[wid] = wy;
        }
        __syncthreads();
        if (wid == 0) {
            float m0 = warp_min(s_r0[lane]);
            float m1 = warp_max(s_r1[lane]);
            float a  = warp_sum(s_r2[lane]);
            float b  = warp_sum(s_r3[lane]);
            float c  = warp_sum(s_r4[lane]);
            if (lane == 0) {
                const float rcp = 1.0f / m1;     // reference divides by max (not max-min)
                s_bmin = m0;
                s_rcp  = rcp;
                // zeta = sum((v - min)/max) = (S - HW*min)/max
                const float denom = a - (float)HW * m0;
                zeta_out[p] = denom * rcp;
                // kp = round(((S*w - min*Sum_w)/max) / zeta) — the /max cancels
                kp_out[(size_t)p * 2 + 0] = rintf((b - m0 * SUM_XW) / denom);
                kp_out[(size_t)p * 2 + 1] = rintf((c - m0 * SUM_XW) / denom);
            }
        }
        __syncthreads();

        const float bmin = s_bmin;
        const float rcp  = s_rcp;

        // ---- Normalize + stream out current plane ----
        float4* __restrict__ op = reinterpret_cast<float4*>(map_out) + (size_t)p * V4;
        #pragma unroll
        for (int i = 0; i < PER; ++i) {
            float4 o;
            o.x = (v[i].x - bmin) * rcp;
            o.y = (v[i].y - bmin) * rcp;
            o.z = (v[i].z - bmin) * rcp;
            o.w = (v[i].w - bmin) * rcp;
            __stcs(&op[tid + i * THREADS], o);
        }

        // ---- Rotate pipeline: consume prefetched regs, accumulate stats ----
        if (has_next) {
            lmin = FLT_MAX; lmax = -FLT_MAX; sr = 0.f; sxr = 0.f; syr = 0.f;
            #pragma unroll
            for (int i = 0; i < PER; ++i) {
                v[i] = u[i];
                lmin = fminf(lmin, fminf(fminf(v[i].x, v[i].y), fminf(v[i].z, v[i].w)));
                lmax = fmaxf(lmax, fmaxf(fmaxf(v[i].x, v[i].y), fmaxf(v[i].z, v[i].w)));
                const int base = (tid + i * THREADS) << 2;
                const float x0 = (float)(base & (W_DIM - 1));
                const float yy = (float)(base >> 7);
                const float s4 = (v[i].x + v[i].y) + (v[i].z + v[i].w);
                sr  += s4;
                sxr += v[i].x * x0 + v[i].y * (x0 + 1.f) + v[i].z * (x0 + 2.f) + v[i].w * (x0 + 3.f);
                syr += s4 * yy;
            }
        }
        p = pn;
    }
}

extern "C" void kernel_launch(void* const* d_in, const int* in_sizes, int n_in,
                              void* d_out, int out_size)
{
    const float* in = (const float*)d_in[0];
    const int total  = in_sizes[0];        // B*C*H*W
    const int planes = total / HW;         // B*C = 6400

    float* map  = (float*)d_out;                       // [B,C,H,W]
    float* kp   = map + (size_t)total;                 // [B,C,2]
    float* zeta = kp + (size_t)planes * 2;             // [B,C]

    int dev = 0, sms = 148;
    cudaGetDevice(&dev);
    cudaDeviceGetAttribute(&sms, cudaDevAttrMultiProcessorCount, dev);

    hm2kp_kernel<<<sms, THREADS>>>(in, map, kp, zeta, planes);
}

// round 4
// speedup vs baseline: 1.1103x; 1.1103x over previous
#include <cuda_runtime.h>
#include <cfloat>

// Problem geometry (fixed by the reference): planes of 128x128, B*C planes.
constexpr int W_DIM   = 128;
constexpr int HW      = 128 * 128;     // 16384 elements per (b,c) plane
constexpr int THREADS = 512;
constexpr int V4      = HW / 4;        // 4096 float4 per plane
constexpr int PER     = V4 / THREADS;  // 8 float4 per thread

__device__ __forceinline__ float warp_sum(float v) {
    #pragma unroll
    for (int o = 16; o > 0; o >>= 1) v += __shfl_down_sync(0xffffffffu, v, o);
    return v;
}
__device__ __forceinline__ float warp_min(float v) {
    #pragma unroll
    for (int o = 16; o > 0; o >>= 1) v = fminf(v, __shfl_down_sync(0xffffffffu, v, o));
    return v;
}
__device__ __forceinline__ float warp_max(float v) {
    #pragma unroll
    for (int o = 16; o > 0; o >>= 1) v = fmaxf(v, __shfl_down_sync(0xffffffffu, v, o));
    return v;
}

__global__ __launch_bounds__(THREADS, 4)
void hm2kp_kernel(const float* __restrict__ in,
                  float* __restrict__ map_out,
                  float* __restrict__ kp_out,
                  float* __restrict__ zeta_out)
{
    __shared__ float s_r0[16], s_r1[16], s_r2[16];
    __shared__ float s_bmin, s_rcp;

    const int bc   = blockIdx.x;
    const int tid  = threadIdx.x;
    const int lane = tid & 31;
    const int wid  = tid >> 5;

    const float4* __restrict__ inp  = reinterpret_cast<const float4*>(in) + (size_t)bc * V4;
    float4* __restrict__       outp = reinterpret_cast<float4*>(map_out) + (size_t)bc * V4;

    // ---- Pass A: cached read (fills L1/L2), min/max only. No data staging,
    //      so registers stay tiny -> 4 CTAs/SM -> 4 independent barrier
    //      domains keeping the memory pipes fed through each reduce. ----
    float lmin = FLT_MAX, lmax = -FLT_MAX;
    #pragma unroll
    for (int i = 0; i < PER; ++i) {
        const float4 t = __ldg(&inp[tid + i * THREADS]);
        lmin = fminf(lmin, fminf(fminf(t.x, t.y), fminf(t.z, t.w)));
        lmax = fmaxf(lmax, fmaxf(fmaxf(t.x, t.y), fmaxf(t.z, t.w)));
    }

    // ---- Block reduce min/max (16 warps) ----
    lmin = warp_min(lmin);
    lmax = warp_max(lmax);
    if (lane == 0) { s_r0[wid] = lmin; s_r1[wid] = lmax; }
    __syncthreads();
    if (wid == 0) {
        float m0 = (lane < 16) ? s_r0[lane] :  FLT_MAX;
        float m1 = (lane < 16) ? s_r1[lane] : -FLT_MAX;
        m0 = warp_min(m0);
        m1 = warp_max(m1);
        if (lane == 0) { s_bmin = m0; s_rcp = 1.0f / m1; }  // ref divides by max
    }
    __syncthreads();

    const float bmin = s_bmin;
    const float rcp  = s_rcp;

    // ---- Pass B: re-read (L1/L2 hit), normalize, store, accumulate the
    //      three reductions on NORMALIZED values (matches reference numerics). ----
    float sum = 0.f, sx = 0.f, sy = 0.f;
    #pragma unroll
    for (int i = 0; i < PER; ++i) {
        const int i4   = tid + i * THREADS;
        const float4 t = __ldg(&inp[i4]);

        const float m0 = (t.x - bmin) * rcp;
        const float m1 = (t.y - bmin) * rcp;
        const float m2 = (t.z - bmin) * rcp;
        const float m3 = (t.w - bmin) * rcp;

        const int base = i4 << 2;                     // element index in plane
        const float x0 = (float)(base & (W_DIM - 1));
        const float yy = (float)(base >> 7);          // row (constant per float4)

        const float s4 = (m0 + m1) + (m2 + m3);
        sum += s4;
        sx  += m0 * x0 + m1 * (x0 + 1.f) + m2 * (x0 + 2.f) + m3 * (x0 + 3.f);
        sy  += s4 * yy;

        __stcs(&outp[i4], make_float4(m0, m1, m2, m3));
    }

    // ---- Block reduce the three sums ----
    sum = warp_sum(sum);
    sx  = warp_sum(sx);
    sy  = warp_sum(sy);
    if (lane == 0) { s_r0[wid] = sum; s_r1[wid] = sx; s_r2[wid] = sy; }
    __syncthreads();
    if (wid == 0) {
        float a = (lane < 16) ? s_r0[lane] : 0.f;
        float b = (lane < 16) ? s_r1[lane] : 0.f;
        float c = (lane < 16) ? s_r2[lane] : 0.f;
        a = warp_sum(a);
        b = warp_sum(b);
        c = warp_sum(c);
        if (lane == 0) {
            kp_out[(size_t)bc * 2 + 0] = rintf(b / a);  // round(get_kp_x / zeta)
            kp_out[(size_t)bc * 2 + 1] = rintf(c / a);  // round(get_kp_y / zeta)
            zeta_out[bc] = a;
        }
    }
}

extern "C" void kernel_launch(void* const* d_in, const int* in_sizes, int n_in,
                              void* d_out, int out_size)
{
    const float* in = (const float*)d_in[0];
    const int total  = in_sizes[0];        // B*C*H*W
    const int planes = total / HW;         // B*C = 6400

    float* map  = (float*)d_out;                       // [B,C,H,W]
    float* kp   = map + (size_t)total;                 // [B,C,2]
    float* zeta = kp + (size_t)planes * 2;             // [B,C]

    hm2kp_kernel<<<planes, THREADS>>>(in, map, kp, zeta);
}